// round 2
// baseline (speedup 1.0000x reference)
#include <cuda_runtime.h>

// BilinearInterpolation: B=16, H=W=512, C=16 fp32.
// One thread per output PIXEL (all 16 channels): index/weight math amortized 4x,
// gathers become LDG.128 with immediate offsets off 4 base addresses,
// store is 64B contiguous per thread (4x STG.128).

#define BB 16
#define HH 512
#define WW 512

__global__ void __launch_bounds__(256)
bilinear_px_kernel(const float4* __restrict__ X,
                   const float* __restrict__ scale,
                   const float* __restrict__ translate,
                   float4* __restrict__ out)
{
    const int p = blockIdx.x * blockDim.x + threadIdx.x;  // pixel id, [0, 16*512*512)
    const int ox = p & 511;
    const int oy = (p >> 9) & 511;
    const int b  = p >> 18;

    const float s  = __ldg(&scale[b]);
    const float tx = __ldg(&translate[2 * b]);
    const float ty = __ldg(&translate[2 * b + 1]);

    const float xc = fmaf((float)ox, 2.0f / 511.0f, -1.0f);
    const float yc = fmaf((float)oy, 2.0f / 511.0f, -1.0f);

    const float x = 0.5f * (fmaf(s, xc, tx) + 1.0f) * (float)WW;
    const float y = 0.5f * (fmaf(s, yc, ty) + 1.0f) * (float)HH;

    // Reference: truncation toward zero, THEN clamp.
    int x0 = (int)x;
    int y0 = (int)y;
    int x1 = x0 + 1;
    int y1 = y0 + 1;
    x0 = min(max(x0, 0), WW - 1);
    x1 = min(max(x1, 0), WW - 1);
    y0 = min(max(y0, 0), HH - 1);
    y1 = min(max(y1, 0), HH - 1);

    const float dx1 = (float)x1 - x, dx0 = x - (float)x0;
    const float dy1 = (float)y1 - y, dy0 = y - (float)y0;
    const float wa = dx1 * dy1;
    const float wb = dx1 * dy0;
    const float wc = dx0 * dy1;
    const float wd = dx0 * dy0;

    // 32-bit quad indices (total tensor = 16M float4 < 2^31)
    const int base = (b << 18) << 2;                 // b*H*W*4 quads
    const int row0 = (y0 << 9) << 2;                 // y0*W*4
    const int row1 = (y1 << 9) << 2;
    const float4* __restrict__ Pa = X + base + row0 + (x0 << 2);
    const float4* __restrict__ Pb = X + base + row1 + (x0 << 2);
    const float4* __restrict__ Pc = X + base + row0 + (x1 << 2);
    const float4* __restrict__ Pd = X + base + row1 + (x1 << 2);

    float4* __restrict__ O = out + (p << 2);

    #pragma unroll
    for (int q = 0; q < 4; ++q) {
        const float4 pa = __ldg(Pa + q);
        const float4 pb = __ldg(Pb + q);
        const float4 pc = __ldg(Pc + q);
        const float4 pd = __ldg(Pd + q);
        float4 o;
        o.x = fmaf(wa, pa.x, fmaf(wb, pb.x, fmaf(wc, pc.x, wd * pd.x)));
        o.y = fmaf(wa, pa.y, fmaf(wb, pb.y, fmaf(wc, pc.y, wd * pd.y)));
        o.z = fmaf(wa, pa.z, fmaf(wb, pb.z, fmaf(wc, pc.z, wd * pd.z)));
        o.w = fmaf(wa, pa.w, fmaf(wb, pb.w, fmaf(wc, pc.w, wd * pd.w)));
        O[q] = o;
    }
}

extern "C" void kernel_launch(void* const* d_in, const int* in_sizes, int n_in,
                              void* d_out, int out_size)
{
    const float* X         = (const float*)d_in[0];
    const float* scale     = (const float*)d_in[1];
    const float* translate = (const float*)d_in[2];

    const int total_px = BB * HH * WW;          // 4,194,304
    const int threads = 256;
    const int blocks = total_px / threads;      // 16,384
    bilinear_px_kernel<<<blocks, threads>>>((const float4*)X, scale, translate,
                                            (float4*)d_out);
}

// round 3
// speedup vs baseline: 1.4779x; 1.4779x over previous
#include <cuda_runtime.h>

// BilinearInterpolation: B=16, H=W=512, C=16 fp32.
// Thread-per-quad layout (R1 memory shape: lanes cover quads contiguously),
// but b/oy derived from blockIdx.z/y so all y-side math + batch params are
// block-uniform (UR datapath). Per-thread work is x-side only.

#define BB 16
#define HH 512
#define WW 512

__global__ void __launch_bounds__(256)
bilinear_u_kernel(const float4* __restrict__ X,
                  const float* __restrict__ scale,
                  const float* __restrict__ translate,
                  float4* __restrict__ out)
{
    // block: 256 threads = 64 pixels x 4 quads. grid = (8, 512, 16).
    const int t  = threadIdx.x;
    const int q  = t & 3;
    const int ox = (blockIdx.x << 6) + (t >> 2);
    const int oy = blockIdx.y;            // uniform
    const int b  = blockIdx.z;            // uniform

    // ---- uniform (per-block) math ----
    const float s  = __ldg(&scale[b]);
    const float tx = __ldg(&translate[2 * b]);
    const float ty = __ldg(&translate[2 * b + 1]);

    const float yc = fmaf((float)oy, 2.0f / 511.0f, -1.0f);
    const float y  = 0.5f * (fmaf(s, yc, ty) + 1.0f) * (float)HH;
    int y0 = (int)y;                      // trunc toward zero (matches astype)
    int y1 = y0 + 1;
    y0 = min(max(y0, 0), HH - 1);
    y1 = min(max(y1, 0), HH - 1);
    const float dy1 = (float)y1 - y;
    const float dy0 = y - (float)y0;

    const int base = b * (HH * WW * 4);   // quad index of batch b
    const int row0 = base + (y0 << 11);   // + y0*W*4
    const int row1 = base + (y1 << 11);

    // ---- per-thread (x-side) math ----
    const float xc = fmaf((float)ox, 2.0f / 511.0f, -1.0f);
    const float x  = 0.5f * (fmaf(s, xc, tx) + 1.0f) * (float)WW;
    int x0 = (int)x;
    int x1 = x0 + 1;
    x0 = min(max(x0, 0), WW - 1);
    x1 = min(max(x1, 0), WW - 1);
    const float dx1 = (float)x1 - x;
    const float dx0 = x - (float)x0;

    const float wa = dx1 * dy1;
    const float wb = dx1 * dy0;
    const float wc = dx0 * dy1;
    const float wd = dx0 * dy0;

    const int c0 = (x0 << 2) + q;
    const int c1 = (x1 << 2) + q;

    const float4 pa = __ldg(X + row0 + c0);
    const float4 pb = __ldg(X + row1 + c0);
    const float4 pc = __ldg(X + row0 + c1);
    const float4 pd = __ldg(X + row1 + c1);

    float4 o;
    o.x = fmaf(wa, pa.x, fmaf(wb, pb.x, fmaf(wc, pc.x, wd * pd.x)));
    o.y = fmaf(wa, pa.y, fmaf(wb, pb.y, fmaf(wc, pc.y, wd * pd.y)));
    o.z = fmaf(wa, pa.z, fmaf(wb, pb.z, fmaf(wc, pc.z, wd * pd.z)));
    o.w = fmaf(wa, pa.w, fmaf(wb, pb.w, fmaf(wc, pc.w, wd * pd.w)));

    // output quad index: ((b*H + oy)*W)*4 + block offset + t  (contiguous per block)
    const int obase = ((b * HH + oy) << 11) + (blockIdx.x << 8);
    out[obase + t] = o;
}

extern "C" void kernel_launch(void* const* d_in, const int* in_sizes, int n_in,
                              void* d_out, int out_size)
{
    const float* X         = (const float*)d_in[0];
    const float* scale     = (const float*)d_in[1];
    const float* translate = (const float*)d_in[2];

    dim3 grid(WW / 64, HH, BB);   // (8, 512, 16) = 65536 blocks
    bilinear_u_kernel<<<grid, 256>>>((const float4*)X, scale, translate,
                                     (float4*)d_out);
}